// round 2
// baseline (speedup 1.0000x reference)
#include <cuda_runtime.h>
#include <cuda_bf16.h>
#include <stdint.h>

#define B_ 64
#define T_ 1024
#define H_ 512
#define E_ 256

#define TILE_T 64
#define KC 32                 // k-chunk size
#define NK (H_/KC)            // 16 chunks
#define LDW 36                // padded row stride in fp32 words (32 + 4) -> conflict-free ldmatrix

#define OFF_PS (B_*H_)                    /* 32768 */
#define OFF_AT (OFF_PS + B_*(T_+1)*H_)    /* 33,619,968 */

// static device scratch (allocation-free)
__device__ __align__(16) float g_Wt[H_*H_];   // [n][k] = tf32-rounded W_prev[k][n]
__device__ float g_comb[B_*H_];
__device__ float g_scores[B_*T_];

// ---- smem layout (fp32 words) ----
#define A_STAGE_W (TILE_T*LDW)            /* 2304 */
#define B_STAGE_W (H_*LDW)                /* 18432 */
#define A0_W      0
#define B0_W      (2*A_STAGE_W)           /* 4608 */
#define COMB_W    (B0_W + 2*B_STAGE_W)    /* 41472 */
#define VW_W      (COMB_W + H_)
#define SC_W      (VW_W + H_)
#define SMEM_W    (SC_W + TILE_T)
#define SMEM_BYTES (SMEM_W*4)             /* 170240 */

__device__ __forceinline__ float to_tf32(float x) {
    uint32_t u;
    asm("cvt.rna.tf32.f32 %0, %1;\n" : "=r"(u) : "f"(x));
    return __uint_as_float(u);
}

// ---------------------------------------------------------------------------
// Prep: W_prev fp32 [k][n] -> g_Wt fp32(tf32-rounded) [n][k]
// ---------------------------------------------------------------------------
__global__ void prep_wt_kernel(const float* __restrict__ Wp) {
    __shared__ float tile[32][33];
    int bx = blockIdx.x * 32, by = blockIdx.y * 32;
    int tx = threadIdx.x, ty = threadIdx.y;   // block (32, 8)
    #pragma unroll
    for (int i = ty; i < 32; i += 8)
        tile[i][tx] = Wp[(by + i) * H_ + bx + tx];
    __syncthreads();
    #pragma unroll
    for (int i = ty; i < 32; i += 8)
        g_Wt[(size_t)(bx + i) * H_ + by + tx] = to_tf32(tile[tx][i]);
}

// ---------------------------------------------------------------------------
// comb[b,k] = s_t[b]@W_s[:,k] + b_s[k] + sum_k_emb[b]@W_t[:,k] + b_t[k]
// (v_b is softmax-shift-invariant -> dropped)
// ---------------------------------------------------------------------------
__global__ void comb_kernel(const float* __restrict__ s_t,
                            const float* __restrict__ ske,
                            const float* __restrict__ W_s,
                            const float* __restrict__ b_s,
                            const float* __restrict__ W_t,
                            const float* __restrict__ b_t) {
    int b = blockIdx.x;
    int k = threadIdx.x;           // 512 threads
    __shared__ float ss[H_];
    __shared__ float se[E_];
    ss[k] = s_t[b * H_ + k];
    if (k < E_) se[k] = ske[b * E_ + k];
    __syncthreads();
    float acc = b_s[k] + b_t[k];
    #pragma unroll 4
    for (int h = 0; h < H_; h++) acc += ss[h] * W_s[h * H_ + k];
    #pragma unroll 4
    for (int e = 0; e < E_; e++) acc += se[e] * W_t[e * H_ + k];
    g_comb[b * H_ + k] = acc;
}

// ---------------------------------------------------------------------------
// tf32 fragment loads via ldmatrix.b16.x4 (16B rows of fp32 data)
// ---------------------------------------------------------------------------
__device__ __forceinline__ void ldsm4(uint32_t* r, uint32_t a) {
    asm volatile("ldmatrix.sync.aligned.m8n8.x4.shared.b16 {%0,%1,%2,%3}, [%4];\n"
                 : "=r"(r[0]), "=r"(r[1]), "=r"(r[2]), "=r"(r[3]) : "r"(a));
}
__device__ __forceinline__ void mma_tf32(float* d, const uint32_t* a, uint32_t b0, uint32_t b1) {
    asm volatile("mma.sync.aligned.m16n8k8.row.col.f32.tf32.tf32.f32 "
                 "{%0,%1,%2,%3},{%4,%5,%6,%7},{%8,%9},{%0,%1,%2,%3};\n"
                 : "+f"(d[0]), "+f"(d[1]), "+f"(d[2]), "+f"(d[3])
                 : "r"(a[0]), "r"(a[1]), "r"(a[2]), "r"(a[3]), "r"(b0), "r"(b1));
}
#define CP_ASYNC16(dst, src) \
    asm volatile("cp.async.cg.shared.global [%0], [%1], 16;\n" :: "r"(dst), "l"(src))

// ---------------------------------------------------------------------------
// Fused score GEMM: scores[b,t] = sum_n tanh( (prev_s[b,t,:]@W_prev)[n] + comb[b,n] ) * v_w[n]
// Block: 512 thr = 16 warps (2m x 8n), tile m64 x n512 (full N), K chunked by 32,
// tf32 mma m16n8k8 fp32-accum, cp.async double-buffered B, warp tile m32 x n64.
// ---------------------------------------------------------------------------
extern "C" __global__ void __launch_bounds__(512, 1)
score_kernel(const float* __restrict__ prev_s, const float* __restrict__ v_w) {
    extern __shared__ float sm[];
    int b = blockIdx.y, t0 = blockIdx.x * TILE_T;
    int tid = threadIdx.x, lane = tid & 31, warp = tid >> 5;
    int wm = warp >> 3, wn = warp & 7;          // wm in {0,1}, wn in 0..7

    // init smem constants
    for (int i = tid; i < H_; i += 512) { sm[COMB_W + i] = g_comb[b * H_ + i]; sm[VW_W + i] = v_w[i]; }
    if (tid < TILE_T) sm[SC_W + tid] = 0.f;

    uint32_t smb = (uint32_t)__cvta_generic_to_shared(sm);

    // A/B load thread mapping
    int ar = tid >> 3, ac = tid & 7;            // A: 64 rows x 8 float4-cols per chunk
    const float4* Asrc = (const float4*)(prev_s + (size_t)(b * T_ + t0) * H_);

    // ldmatrix lane addressing (tf32-as-b16 trick)
    int aRow  = wm * 32 + (lane & 7) + 8 * ((lane >> 3) & 1);
    int aHalf = lane >> 4;                      // +4 words
    uint32_t aBase = smb + (uint32_t)(A0_W + aRow * LDW + aHalf * 4) * 4;
    int bRow  = wn * 64 + (lane & 7) + 8 * (lane >> 4);
    int bHalf = (lane >> 3) & 1;
    uint32_t bBase = smb + (uint32_t)(B0_W + bRow * LDW + bHalf * 4) * 4;

    // ---- prologue: stage 0 ----
    {   // A chunk 0: LDG -> tf32 round -> STS
        float4 v = Asrc[ar * 128 + ac];
        float4 r = make_float4(to_tf32(v.x), to_tf32(v.y), to_tf32(v.z), to_tf32(v.w));
        *(float4*)&sm[A0_W + ar * LDW + ac * 4] = r;
        // B chunk 0 via cp.async
        #pragma unroll
        for (int i = 0; i < 8; i++) {
            int idx = tid + i * 512;
            int n = idx >> 3, c = idx & 7;
            uint32_t dst = smb + (uint32_t)(B0_W + n * LDW + c * 4) * 4;
            CP_ASYNC16(dst, g_Wt + (size_t)n * H_ + c * 4);
        }
        asm volatile("cp.async.commit_group;\n" ::: "memory");
    }

    float acc[2][8][4];
    #pragma unroll
    for (int mi = 0; mi < 2; mi++)
        #pragma unroll
        for (int ni = 0; ni < 8; ni++)
            #pragma unroll
            for (int j = 0; j < 4; j++) acc[mi][ni][j] = 0.f;

    for (int kc = 0; kc < NK; kc++) {
        int stage = kc & 1;
        bool havenext = (kc + 1 < NK);
        float4 avn;
        if (havenext) {
            int kn = kc + 1, sn = kn & 1;
            avn = Asrc[ar * 128 + kn * 8 + ac];
            #pragma unroll
            for (int i = 0; i < 8; i++) {
                int idx = tid + i * 512;
                int n = idx >> 3, c = idx & 7;
                uint32_t dst = smb + (uint32_t)(B0_W + sn * B_STAGE_W + n * LDW + c * 4) * 4;
                CP_ASYNC16(dst, g_Wt + (size_t)n * H_ + kn * KC + c * 4);
            }
            asm volatile("cp.async.commit_group;\n" ::: "memory");
            asm volatile("cp.async.wait_group 1;\n" ::: "memory");
        } else {
            asm volatile("cp.async.wait_group 0;\n" ::: "memory");
        }
        __syncthreads();   // stage data visible to all
        if (havenext) {    // store next A chunk (target stage != compute stage; safe)
            int sn = (kc + 1) & 1;
            float4 r = make_float4(to_tf32(avn.x), to_tf32(avn.y), to_tf32(avn.z), to_tf32(avn.w));
            *(float4*)&sm[A0_W + sn * A_STAGE_W + ar * LDW + ac * 4] = r;
        }
        // ---- compute chunk ----
        uint32_t aS = aBase + stage * (A_STAGE_W * 4);
        uint32_t bS = bBase + stage * (B_STAGE_W * 4);
        #pragma unroll
        for (int k8 = 0; k8 < KC / 8; k8++) {
            uint32_t a0[4], a1[4], bb[4][4];
            ldsm4(a0, aS + k8 * 32);
            ldsm4(a1, aS + 16 * LDW * 4 + k8 * 32);
            #pragma unroll
            for (int t = 0; t < 4; t++) ldsm4(bb[t], bS + t * (16 * LDW * 4) + k8 * 32);
            #pragma unroll
            for (int t = 0; t < 4; t++) {
                mma_tf32(acc[0][2 * t],     a0, bb[t][0], bb[t][1]);
                mma_tf32(acc[0][2 * t + 1], a0, bb[t][2], bb[t][3]);
                mma_tf32(acc[1][2 * t],     a1, bb[t][0], bb[t][1]);
                mma_tf32(acc[1][2 * t + 1], a1, bb[t][2], bb[t][3]);
            }
        }
        __syncthreads();   // chunk consumed; stage may be overwritten next iter
    }

    // ---- epilogue: tanh(acc + comb) * vw, reduce over full N ----
    #pragma unroll
    for (int mi = 0; mi < 2; mi++) {
        float p0 = 0.f, p1 = 0.f;    // rows r, r+8
        #pragma unroll
        for (int ni = 0; ni < 8; ni++) {
            int col = wn * 64 + ni * 8 + 2 * (lane & 3);
            float c0 = sm[COMB_W + col],     w0 = sm[VW_W + col];
            float c1 = sm[COMB_W + col + 1], w1 = sm[VW_W + col + 1];
            p0 += tanhf(acc[mi][ni][0] + c0) * w0 + tanhf(acc[mi][ni][1] + c1) * w1;
            p1 += tanhf(acc[mi][ni][2] + c0) * w0 + tanhf(acc[mi][ni][3] + c1) * w1;
        }
        p0 += __shfl_xor_sync(0xffffffffu, p0, 1);
        p0 += __shfl_xor_sync(0xffffffffu, p0, 2);
        p1 += __shfl_xor_sync(0xffffffffu, p1, 1);
        p1 += __shfl_xor_sync(0xffffffffu, p1, 2);
        if ((lane & 3) == 0) {
            int g = lane >> 2;
            atomicAdd(&sm[SC_W + wm * 32 + mi * 16 + g],     p0);
            atomicAdd(&sm[SC_W + wm * 32 + mi * 16 + g + 8], p1);
        }
    }
    __syncthreads();
    if (tid < TILE_T) g_scores[b * T_ + t0 + tid] = sm[SC_W + tid];
}

// ---------------------------------------------------------------------------
// Softmax over T per batch; zero ct_d row; write s_t row of prev_s_new
// ---------------------------------------------------------------------------
extern "C" __global__ void softmax_kernel(const float* __restrict__ s_t, float* __restrict__ out) {
    int b = blockIdx.x, tid = threadIdx.x;   // 256 threads
    __shared__ float e[T_];
    __shared__ float red[256];
    float m = -1e30f;
    for (int i = tid; i < T_; i += 256) { float s = g_scores[b * T_ + i]; e[i] = s; m = fmaxf(m, s); }
    red[tid] = m; __syncthreads();
    for (int s = 128; s > 0; s >>= 1) { if (tid < s) red[tid] = fmaxf(red[tid], red[tid + s]); __syncthreads(); }
    float mx = red[0];
    __syncthreads();
    float sum = 0.f;
    for (int i = tid; i < T_; i += 256) { float v = expf(e[i] - mx); e[i] = v; sum += v; }
    red[tid] = sum; __syncthreads();
    for (int s = 128; s > 0; s >>= 1) { if (tid < s) red[tid] += red[tid + s]; __syncthreads(); }
    float inv = 1.f / red[0];
    float* at_out = out + OFF_AT + (size_t)b * T_;
    for (int i = tid; i < T_; i += 256) at_out[i] = e[i] * inv;
    for (int i = tid; i < H_; i += 256) out[b * H_ + i] = 0.f;          // zero ct_d
    float* pn = out + OFF_PS + (size_t)b * (T_ + 1) * H_ + (size_t)T_ * H_;
    for (int i = tid; i < H_; i += 256) pn[i] = s_t[b * H_ + i];        // concat row
}

// ---------------------------------------------------------------------------
// Fused: prev_s_new copy + ct_d = sum_t at*prev_s (single pass over prev_s)
// ---------------------------------------------------------------------------
extern "C" __global__ void ct_copy_kernel(const float* __restrict__ prev_s, float* __restrict__ out) {
    int b = blockIdx.y, t0 = blockIdx.x * 64;
    int tid = threadIdx.x;   // 256 threads, float2 per thread covers H=512
    const float* at = out + OFF_AT + (size_t)b * T_ + t0;
    const float2* src = (const float2*)(prev_s + (size_t)(b * T_ + t0) * H_);
    float2* dst = (float2*)(out + OFF_PS + (size_t)b * (T_ + 1) * H_ + (size_t)t0 * H_);
    float ax = 0.f, ay = 0.f;
    #pragma unroll 4
    for (int tt = 0; tt < 64; tt++) {
        float a = __ldg(at + tt);
        float2 v = src[tt * 256 + tid];
        dst[tt * 256 + tid] = v;
        ax += a * v.x; ay += a * v.y;
    }
    atomicAdd(out + b * H_ + tid * 2, ax);
    atomicAdd(out + b * H_ + tid * 2 + 1, ay);
}

// ---------------------------------------------------------------------------
extern "C" void kernel_launch(void* const* d_in, const int* in_sizes, int n_in,
                              void* d_out, int out_size) {
    const float* s_t    = (const float*)d_in[0];
    const float* prev_s = (const float*)d_in[1];
    const float* ske    = (const float*)d_in[2];
    const float* W_prev = (const float*)d_in[3];
    const float* W_s    = (const float*)d_in[4];
    const float* b_s    = (const float*)d_in[5];
    const float* W_t    = (const float*)d_in[6];
    const float* b_t    = (const float*)d_in[7];
    const float* v_w    = (const float*)d_in[8];
    // d_in[9] = v_b: softmax-shift-invariant -> unused
    float* out = (float*)d_out;

    cudaFuncSetAttribute(score_kernel, cudaFuncAttributeMaxDynamicSharedMemorySize, SMEM_BYTES);

    prep_wt_kernel<<<dim3(16, 16), dim3(32, 8)>>>(W_prev);
    comb_kernel<<<B_, H_>>>(s_t, ske, W_s, b_s, W_t, b_t);
    score_kernel<<<dim3(T_ / TILE_T, B_), 512, SMEM_BYTES>>>(prev_s, v_w);
    softmax_kernel<<<B_, 256>>>(s_t, out);
    ct_copy_kernel<<<dim3(T_ / 64, B_), 256>>>(prev_s, out);
}

// round 8
// speedup vs baseline: 1.4798x; 1.4798x over previous
#include <cuda_runtime.h>
#include <cuda_fp16.h>
#include <stdint.h>

#define B_ 64
#define T_ 1024
#define H_ 512
#define E_ 256

#define TILE_T 64
#define KC 64                 // k-chunk (halfs)
#define NKC (H_/KC)           /* 8 */
#define LDH 72                // padded row stride in halfs (64+8 -> 16B rotation, conflict-free ldmatrix)

#define OFF_PS (B_*H_)                    /* 32768 */
#define OFF_AT (OFF_PS + B_*(T_+1)*H_)    /* 33,619,968 */

// static device scratch (allocation-free)
__device__ __align__(16) __half g_Wt[H_*H_];  // [n][k] = fp16(W_prev[k][n])
__device__ float g_comb[B_*H_];
__device__ float g_scores[B_*T_];

// ---- smem layout (bytes) ----
#define ASTAGE_B   (TILE_T*LDH*2)         /* 9216 */
#define BSTAGE_B   (H_*LDH*2)             /* 73728 */
#define A0_OFF     0
#define B0_OFF     (2*ASTAGE_B)           /* 18432 */
#define COMB_OFF   (B0_OFF + 2*BSTAGE_B)  /* 165888 */
#define VW_OFF     (COMB_OFF + H_*4)      /* 167936 */
#define SC_OFF     (VW_OFF + H_*4)        /* 169984 */
#define SMEM_BYTES (SC_OFF + TILE_T*4)    /* 170240 */

__device__ __forceinline__ void ldsm4(uint32_t* r, uint32_t a) {
    asm volatile("ldmatrix.sync.aligned.m8n8.x4.shared.b16 {%0,%1,%2,%3}, [%4];\n"
                 : "=r"(r[0]), "=r"(r[1]), "=r"(r[2]), "=r"(r[3]) : "r"(a));
}
__device__ __forceinline__ void mma16816(float* d, const uint32_t* a, uint32_t b0, uint32_t b1) {
    asm volatile("mma.sync.aligned.m16n8k16.row.col.f32.f16.f16.f32 "
                 "{%0,%1,%2,%3},{%4,%5,%6,%7},{%8,%9},{%0,%1,%2,%3};\n"
                 : "+f"(d[0]), "+f"(d[1]), "+f"(d[2]), "+f"(d[3])
                 : "r"(a[0]), "r"(a[1]), "r"(a[2]), "r"(a[3]), "r"(b0), "r"(b1));
}
#define CP_ASYNC16(dst, src) \
    asm volatile("cp.async.cg.shared.global [%0], [%1], 16;\n" :: "r"(dst), "l"(src))

__device__ __forceinline__ float fast_tanh(float x){
    // tanh(x) = 1 - 2/(e^{2x}+1); inf-safe both ends, abs err ~1e-6
    float ex = __expf(2.0f * x);
    return 1.0f - __fdividef(2.0f, ex + 1.0f);
}

// ---------------------------------------------------------------------------
// Prep: W_prev fp32 [k][n] -> g_Wt fp16 [n][k]
// ---------------------------------------------------------------------------
__global__ void prep_wt_kernel(const float* __restrict__ Wp) {
    __shared__ float tile[32][33];
    int bx = blockIdx.x * 32, by = blockIdx.y * 32;
    int tx = threadIdx.x, ty = threadIdx.y;   // block (32, 8)
    #pragma unroll
    for (int i = ty; i < 32; i += 8)
        tile[i][tx] = Wp[(by + i) * H_ + bx + tx];
    __syncthreads();
    #pragma unroll
    for (int i = ty; i < 32; i += 8)
        g_Wt[(size_t)(bx + i) * H_ + by + tx] = __float2half_rn(tile[tx][i]);
}

// ---------------------------------------------------------------------------
// comb[b,k] = s_t[b]@W_s[:,k] + b_s[k] + sum_k_emb[b]@W_t[:,k] + b_t[k]
// (v_b is softmax-shift-invariant -> dropped)
// ---------------------------------------------------------------------------
__global__ void comb_kernel(const float* __restrict__ s_t,
                            const float* __restrict__ ske,
                            const float* __restrict__ W_s,
                            const float* __restrict__ b_s,
                            const float* __restrict__ W_t,
                            const float* __restrict__ b_t) {
    int b = blockIdx.x;
    int k = threadIdx.x;           // 512 threads
    __shared__ float ss[H_];
    __shared__ float se[E_];
    ss[k] = s_t[b * H_ + k];
    if (k < E_) se[k] = ske[b * E_ + k];
    __syncthreads();
    float acc = b_s[k] + b_t[k];
    #pragma unroll 4
    for (int h = 0; h < H_; h++) acc += ss[h] * W_s[h * H_ + k];
    #pragma unroll 4
    for (int e = 0; e < E_; e++) acc += se[e] * W_t[e * H_ + k];
    g_comb[b * H_ + k] = acc;
}

// ---------------------------------------------------------------------------
// Fused score GEMM (fp16 mma.sync m16n8k16, fp32 accum):
//   scores[b,t] = sum_n tanh( (prev_s[b,t,:]@W_prev)[n] + comb[b,n] ) * v_w[n]
// Block: 512 thr = 16 warps (2m x 8n), tile m64 x n512 (full N), K chunked
// by 64, cp.async double-buffered B, LDG->cvt->STS double-buffered A,
// warp tile m32 x n64. Same pipeline discipline as the R2-passing kernel.
// ---------------------------------------------------------------------------
extern "C" __global__ void __launch_bounds__(512, 1)
score_kernel(const float* __restrict__ prev_s, const float* __restrict__ v_w) {
    extern __shared__ char smem[];
    __half* As = (__half*)(smem + A0_OFF);
    float* combs = (float*)(smem + COMB_OFF);
    float* vws   = (float*)(smem + VW_OFF);
    float* sc    = (float*)(smem + SC_OFF);

    int b = blockIdx.y, t0 = blockIdx.x * TILE_T;
    int tid = threadIdx.x, lane = tid & 31, warp = tid >> 5;
    int wm = warp >> 3, wn = warp & 7;          // wm in {0,1}, wn in 0..7

    for (int i = tid; i < H_; i += 512) { combs[i] = g_comb[b * H_ + i]; vws[i] = v_w[i]; }
    if (tid < TILE_T) sc[tid] = 0.f;

    uint32_t smb;
    asm("{ .reg .u64 t; cvta.to.shared.u64 t, %1; cvt.u32.u64 %0, t; }" : "=r"(smb) : "l"(smem));

    // A load mapping: per chunk 64 rows x 16 float4 = 1024 -> 2 per thread
    int ar = tid >> 4, ac4 = tid & 15;          // with i-stride 512: ar+32
    const float* Abase = prev_s + (size_t)(b * T_ + t0) * H_;

    // B load mapping: per chunk 512 rows x 8 x 16B = 4096 -> 8 per thread
    int bn = tid >> 3, bc = tid & 7;            // i-stride 512 -> n += 64

    // ldmatrix lane addressing (fp16, proven R1 mapping)
    int aRow  = wm * 32 + (lane & 7) + 8 * ((lane >> 3) & 1);
    int aK    = 8 * (lane >> 4);
    uint32_t aBase = smb + A0_OFF + (uint32_t)(aRow * LDH + aK) * 2;
    int bRow  = wn * 64 + (lane & 7) + 8 * (lane >> 4);
    int bK    = 8 * ((lane >> 3) & 1);
    uint32_t bBase = smb + B0_OFF + (uint32_t)(bRow * LDH + bK) * 2;

    // ---- prologue: chunk 0 -> stage 0 ----
    {
        #pragma unroll
        for (int i = 0; i < 8; i++) {
            int n = bn + i * 64;
            uint32_t dst = smb + B0_OFF + (uint32_t)(n * LDH) * 2 + bc * 16;
            CP_ASYNC16(dst, g_Wt + (size_t)n * H_ + bc * 8);
        }
        asm volatile("cp.async.commit_group;\n" ::: "memory");
        #pragma unroll
        for (int i = 0; i < 2; i++) {
            int r = ar + i * 32;
            float4 v = *(const float4*)(Abase + (size_t)r * H_ + ac4 * 4);
            __half2 p0 = __floats2half2_rn(v.x, v.y);
            __half2 p1 = __floats2half2_rn(v.z, v.w);
            __half2* dst = (__half2*)(As + r * LDH + ac4 * 4);
            dst[0] = p0; dst[1] = p1;
        }
        asm volatile("cp.async.wait_group 0;\n" ::: "memory");
        __syncthreads();
    }

    float acc[2][8][4];
    #pragma unroll
    for (int mi = 0; mi < 2; mi++)
        #pragma unroll
        for (int ni = 0; ni < 8; ni++)
            #pragma unroll
            for (int j = 0; j < 4; j++) acc[mi][ni][j] = 0.f;

    for (int kc = 0; kc < NKC; kc++) {
        int s = kc & 1, sp = s ^ 1;
        bool more = (kc + 1 < NKC);
        float4 av[2];
        if (more) {
            const __half* Bsrc = g_Wt + (kc + 1) * KC;
            #pragma unroll
            for (int i = 0; i < 8; i++) {
                int n = bn + i * 64;
                uint32_t dst = smb + B0_OFF + sp * BSTAGE_B + (uint32_t)(n * LDH) * 2 + bc * 16;
                CP_ASYNC16(dst, Bsrc + (size_t)n * H_ + bc * 8);
            }
            asm volatile("cp.async.commit_group;\n" ::: "memory");
            const float* Asrc = Abase + (kc + 1) * KC;
            #pragma unroll
            for (int i = 0; i < 2; i++) {
                int r = ar + i * 32;
                av[i] = *(const float4*)(Asrc + (size_t)r * H_ + ac4 * 4);
            }
            asm volatile("cp.async.wait_group 1;\n" ::: "memory");  // stage s B ready
        } else {
            asm volatile("cp.async.wait_group 0;\n" ::: "memory");
        }
        __syncthreads();
        if (more) {   // store next A into stage sp (not read until next iter's sync)
            #pragma unroll
            for (int i = 0; i < 2; i++) {
                int r = ar + i * 32;
                __half2 p0 = __floats2half2_rn(av[i].x, av[i].y);
                __half2 p1 = __floats2half2_rn(av[i].z, av[i].w);
                __half2* dst = (__half2*)(As + sp * (ASTAGE_B / 2) + r * LDH + ac4 * 4);
                dst[0] = p0; dst[1] = p1;
            }
        }
        // ---- compute chunk kc from stage s ----
        uint32_t aS = aBase + s * ASTAGE_B;
        uint32_t bS = bBase + s * BSTAGE_B;
        #pragma unroll
        for (int k16 = 0; k16 < KC / 16; k16++) {
            uint32_t a0[4], a1[4], bb[4][4];
            ldsm4(a0, aS + k16 * 32);
            ldsm4(a1, aS + 16 * LDH * 2 + k16 * 32);
            #pragma unroll
            for (int t = 0; t < 4; t++) ldsm4(bb[t], bS + t * (16 * LDH * 2) + k16 * 32);
            #pragma unroll
            for (int t = 0; t < 4; t++) {
                mma16816(acc[0][2 * t],     a0, bb[t][0], bb[t][1]);
                mma16816(acc[0][2 * t + 1], a0, bb[t][2], bb[t][3]);
                mma16816(acc[1][2 * t],     a1, bb[t][0], bb[t][1]);
                mma16816(acc[1][2 * t + 1], a1, bb[t][2], bb[t][3]);
            }
        }
        __syncthreads();
    }

    // ---- epilogue: tanh(acc + comb) * vw, reduce over full N ----
    #pragma unroll
    for (int mi = 0; mi < 2; mi++) {
        float p0 = 0.f, p1 = 0.f;    // rows r, r+8
        #pragma unroll
        for (int ni = 0; ni < 8; ni++) {
            int col = wn * 64 + ni * 8 + 2 * (lane & 3);
            float c0 = combs[col],     w0 = vws[col];
            float c1 = combs[col + 1], w1 = vws[col + 1];
            p0 += fast_tanh(acc[mi][ni][0] + c0) * w0 + fast_tanh(acc[mi][ni][1] + c1) * w1;
            p1 += fast_tanh(acc[mi][ni][2] + c0) * w0 + fast_tanh(acc[mi][ni][3] + c1) * w1;
        }
        p0 += __shfl_xor_sync(0xffffffffu, p0, 1);
        p0 += __shfl_xor_sync(0xffffffffu, p0, 2);
        p1 += __shfl_xor_sync(0xffffffffu, p1, 1);
        p1 += __shfl_xor_sync(0xffffffffu, p1, 2);
        if ((lane & 3) == 0) {
            int g = lane >> 2;
            atomicAdd(&sc[wm * 32 + mi * 16 + g],     p0);
            atomicAdd(&sc[wm * 32 + mi * 16 + g + 8], p1);
        }
    }
    __syncthreads();
    if (tid < TILE_T) g_scores[b * T_ + t0 + tid] = sc[tid];
}

// ---------------------------------------------------------------------------
// Softmax over T per batch; zero ct_d row; write s_t row of prev_s_new
// ---------------------------------------------------------------------------
extern "C" __global__ void softmax_kernel(const float* __restrict__ s_t, float* __restrict__ out) {
    int b = blockIdx.x, tid = threadIdx.x;   // 256 threads
    __shared__ float e[T_];
    __shared__ float red[256];
    float m = -1e30f;
    for (int i = tid; i < T_; i += 256) { float s = g_scores[b * T_ + i]; e[i] = s; m = fmaxf(m, s); }
    red[tid] = m; __syncthreads();
    for (int s = 128; s > 0; s >>= 1) { if (tid < s) red[tid] = fmaxf(red[tid], red[tid + s]); __syncthreads(); }
    float mx = red[0];
    __syncthreads();
    float sum = 0.f;
    for (int i = tid; i < T_; i += 256) { float v = expf(e[i] - mx); e[i] = v; sum += v; }
    red[tid] = sum; __syncthreads();
    for (int s = 128; s > 0; s >>= 1) { if (tid < s) red[tid] += red[tid + s]; __syncthreads(); }
    float inv = 1.f / red[0];
    float* at_out = out + OFF_AT + (size_t)b * T_;
    for (int i = tid; i < T_; i += 256) at_out[i] = e[i] * inv;
    for (int i = tid; i < H_; i += 256) out[b * H_ + i] = 0.f;          // zero ct_d
    float* pn = out + OFF_PS + (size_t)b * (T_ + 1) * H_ + (size_t)T_ * H_;
    for (int i = tid; i < H_; i += 256) pn[i] = s_t[b * H_ + i];        // concat row
}

// ---------------------------------------------------------------------------
// Fused: prev_s_new copy + ct_d = sum_t at*prev_s (single pass over prev_s)
// ---------------------------------------------------------------------------
extern "C" __global__ void ct_copy_kernel(const float* __restrict__ prev_s, float* __restrict__ out) {
    int b = blockIdx.y, t0 = blockIdx.x * 64;
    int tid = threadIdx.x;   // 256 threads, float2 per thread covers H=512
    const float* at = out + OFF_AT + (size_t)b * T_ + t0;
    const float2* src = (const float2*)(prev_s + (size_t)(b * T_ + t0) * H_);
    float2* dst = (float2*)(out + OFF_PS + (size_t)b * (T_ + 1) * H_ + (size_t)t0 * H_);
    float ax = 0.f, ay = 0.f;
    #pragma unroll 4
    for (int tt = 0; tt < 64; tt++) {
        float a = __ldg(at + tt);
        float2 v = src[tt * 256 + tid];
        dst[tt * 256 + tid] = v;
        ax += a * v.x; ay += a * v.y;
    }
    atomicAdd(out + b * H_ + tid * 2, ax);
    atomicAdd(out + b * H_ + tid * 2 + 1, ay);
}

// ---------------------------------------------------------------------------
extern "C" void kernel_launch(void* const* d_in, const int* in_sizes, int n_in,
                              void* d_out, int out_size) {
    const float* s_t    = (const float*)d_in[0];
    const float* prev_s = (const float*)d_in[1];
    const float* ske    = (const float*)d_in[2];
    const float* W_prev = (const float*)d_in[3];
    const float* W_s    = (const float*)d_in[4];
    const float* b_s    = (const float*)d_in[5];
    const float* W_t    = (const float*)d_in[6];
    const float* b_t    = (const float*)d_in[7];
    const float* v_w    = (const float*)d_in[8];
    // d_in[9] = v_b: softmax-shift-invariant -> unused
    float* out = (float*)d_out;

    cudaFuncSetAttribute(score_kernel, cudaFuncAttributeMaxDynamicSharedMemorySize, SMEM_BYTES);

    prep_wt_kernel<<<dim3(16, 16), dim3(32, 8)>>>(W_prev);
    comb_kernel<<<B_, H_>>>(s_t, ske, W_s, b_s, W_t, b_t);
    score_kernel<<<dim3(T_ / TILE_T, B_), 512, SMEM_BYTES>>>(prev_s, v_w);
    softmax_kernel<<<B_, 256>>>(s_t, out);
    ct_copy_kernel<<<dim3(T_ / 64, B_), 256>>>(prev_s, out);
}